// round 16
// baseline (speedup 1.0000x reference)
#include <cuda_runtime.h>
#include <math.h>

// Static geometry: x shape (1, 3, 32, 512, 512), patch 32x32
#define C       3
#define T       32
#define H       512
#define W       512
#define PS      32
#define NPATCH  (T * (H/PS) * (W/PS))   // 8192 worker CTAs (+1 finalizer)
#define PATCH_ELEMS (C * PS * PS)       // 3072

// Float bits of per-frame max patch-sum; sums >= 0 so int-punned atomicMax
// preserves float order and zero-init is the identity. Reset by the
// finalizer each iteration -> graph-replay safe.
__device__ int          g_frame_max[T];   // zero-initialized
__device__ unsigned int g_count;          // zero-initialized

__global__ __launch_bounds__(256, 8)
void patch_loss_kernel(const float* __restrict__ x,
                       const float* __restrict__ xr,
                       float* __restrict__ out) {
    // ---------------- Finalizer CTA (block 0) ----------------
    if (blockIdx.x == 0) {
        const int tid = threadIdx.x;
        if (tid < 32) {
            if (tid == 0) {
                unsigned int c;
                // Relaxed bounded spin on ONE word.
                for (unsigned int it = 0; it < (1u << 24); ++it) {
                    asm volatile("ld.relaxed.gpu.global.u32 %0, [%1];"
                                 : "=r"(c) : "l"(&g_count) : "memory");
                    if (c >= (unsigned int)NPATCH) break;
                    __nanosleep(32);
                }
                // Settle window: workers' count-adds are relaxed, so a
                // leader's earlier frame-max RED could still be in flight
                // when its count RED is visible. 1us >> any L2 queue skew.
                __nanosleep(1024);
            }
            __syncwarp();
            float fm = fmaxf(__int_as_float(__ldcg(&g_frame_max[tid])), 0.0f);
#pragma unroll
            for (int off = 16; off > 0; off >>= 1)
                fm += __shfl_down_sync(0xFFFFFFFFu, fm, off);

            // Reset device state for the next graph replay.
            g_frame_max[tid] = 0;
            if (tid == 0) {
                g_count = 0u;
                const float scale = 0.5f / ((float)PATCH_ELEMS * (float)T);
                out[0] = logf(fm * scale);
            }
        }
        return;
    }

    // ---------------- Worker CTA: one 32x32 patch ----------------
    const int patch = blockIdx.x - 1;      // [0, 8192)
    const int t   = patch >> 8;            // frame
    const int rem = patch & 255;
    const int ih  = rem >> 4;
    const int iw  = rem & 15;

    const int tid = threadIdx.x;           // [0, 256)
    const int r = tid >> 3;                // row within patch [0,32)
    const int q = tid & 7;                 // float4 index within row [0,8)

    const int hrow  = ih * PS + r;
    const int base0 = (t * H + hrow) * W + iw * PS + q * 4;
    const int cstride = T * H * W;

    float s = 0.0f;
#pragma unroll
    for (int c = 0; c < C; ++c) {
        const int idx = base0 + c * cstride;
        const float4 a = __ldg(reinterpret_cast<const float4*>(x  + idx));
        const float4 b = __ldg(reinterpret_cast<const float4*>(xr + idx));
        s += fabsf(a.x - b.x) + fabsf(a.y - b.y)
           + fabsf(a.z - b.z) + fabsf(a.w - b.w);
    }

    // Block reduction: warp shfl then smem across 8 warps.
#pragma unroll
    for (int off = 16; off > 0; off >>= 1)
        s += __shfl_down_sync(0xFFFFFFFFu, s, off);

    __shared__ float warp_sums[8];
    const int lane = tid & 31;
    const int wid  = tid >> 5;
    if (lane == 0) warp_sums[wid] = s;
    __syncthreads();

    if (wid == 0) {
        float v = (lane < 8) ? warp_sums[lane] : 0.0f;
#pragma unroll
        for (int off = 4; off > 0; off >>= 1)
            v += __shfl_down_sync(0xFFFFFFFFu, v, off);
        if (lane == 0) {
            // Both reductions fully relaxed + fire-and-forget: zero stalls,
            // CTA retires immediately after issue.
            atomicMax(&g_frame_max[t], __float_as_int(v));   // RED.MAX
            asm volatile("red.relaxed.gpu.global.add.u32 [%0], 1;"
                         :: "l"(&g_count) : "memory");       // RED.ADD
        }
    }
}

extern "C" void kernel_launch(void* const* d_in, const int* in_sizes, int n_in,
                              void* d_out, int out_size) {
    const float* x  = (const float*)d_in[0];
    const float* xr = (const float*)d_in[1];
    float* out = (float*)d_out;

    patch_loss_kernel<<<NPATCH + 1, 256>>>(x, xr, out);
}